// round 2
// baseline (speedup 1.0000x reference)
#include <cuda_runtime.h>
#include <math.h>

#define NN 4096
#define DD 256
#define HH 4
#define HD 64
#define D3 768

// ---------------- scratch (device globals; no allocation) ----------------
// NOTE: never reference these directly from device code AND pass from host —
// host code sees the shadow symbol (ATS makes it silently "work" on GB300).
// All kernels take pointers; host resolves via cudaGetSymbolAddress.
__device__ float g_h   [NN * DD];
__device__ float g_xl  [NN * DD];
__device__ float g_x1  [NN * DD];
__device__ float g_qkv [NN * D3];
__device__ float g_attn[NN * DD];
__device__ float g_ao  [NN * DD];
__device__ float g_x2  [NN * DD];
__device__ float g_h1  [NN * 2 * DD];
__device__ float g_f2  [NN * DD];
__device__ float g_dinv[NN];
__device__ int   g_deg [NN];

// ---------------- degree / dinv ----------------
__global__ void zero_deg_kernel(int* deg) {
    int i = blockIdx.x * blockDim.x + threadIdx.x;
    if (i < NN) deg[i] = 0;
}
__global__ void count_deg_kernel(const int* __restrict__ dst, int* deg, int E) {
    int e = blockIdx.x * blockDim.x + threadIdx.x;
    if (e < E) atomicAdd(&deg[dst[e]], 1);
}
__global__ void dinv_kernel(const int* __restrict__ deg, float* __restrict__ dinv) {
    int i = blockIdx.x * blockDim.x + threadIdx.x;
    if (i < NN) dinv[i] = rsqrtf((float)deg[i] + 1.0f);
}

// ---------------- self-loop init: xl = h * dinv^2 + b_gcn ----------------
__global__ void selfloop_kernel(const float* __restrict__ h,
                                const float* __restrict__ dinv,
                                const float* __restrict__ b_gcn,
                                float* __restrict__ xl) {
    int idx = blockIdx.x * blockDim.x + threadIdx.x;   // float4 index
    if (idx >= NN * DD / 4) return;
    int i  = idx / (DD / 4);
    int d4 = idx % (DD / 4);
    float c = dinv[i]; c = c * c;
    float4 h4 = *(const float4*)&h[i * DD + d4 * 4];
    float4 b4 = *(const float4*)&b_gcn[d4 * 4];
    float4 o;
    o.x = h4.x * c + b4.x; o.y = h4.y * c + b4.y;
    o.z = h4.z * c + b4.z; o.w = h4.w * c + b4.w;
    *(float4*)&xl[i * DD + d4 * 4] = o;
}

// ---------------- edge scatter: xl[dst] += h[src] * dinv[src]*dinv[dst] ----
__global__ void edge_scatter_kernel(const int* __restrict__ src,
                                    const int* __restrict__ dst,
                                    const float* __restrict__ h,
                                    const float* __restrict__ dinv,
                                    float* __restrict__ xl, int E) {
    int e    = blockIdx.x * 4 + (threadIdx.x >> 6);
    int lane = threadIdx.x & 63;
    if (e >= E) return;
    int s = src[e], t = dst[e];
    float c = dinv[s] * dinv[t];
    float4 h4 = *(const float4*)&h[s * DD + lane * 4];
    float* o = &xl[t * DD + lane * 4];
    atomicAdd(o + 0, h4.x * c);
    atomicAdd(o + 1, h4.y * c);
    atomicAdd(o + 2, h4.z * c);
    atomicAdd(o + 3, h4.w * c);
}

// ---------------- layernorm: out = LN(a + b) * g + beta ----------------
__global__ void ln_kernel(const float* __restrict__ a, const float* __restrict__ b,
                          const float* __restrict__ g, const float* __restrict__ beta,
                          float* __restrict__ out) {
    int r = blockIdx.x, d = threadIdx.x;   // 256 threads
    float v = a[r * DD + d] + b[r * DD + d];
    float s1 = v, s2 = v * v;
    #pragma unroll
    for (int off = 16; off > 0; off >>= 1) {
        s1 += __shfl_xor_sync(0xffffffffu, s1, off);
        s2 += __shfl_xor_sync(0xffffffffu, s2, off);
    }
    __shared__ float ws1[8], ws2[8], bc[2];
    int w = threadIdx.x >> 5;
    if ((threadIdx.x & 31) == 0) { ws1[w] = s1; ws2[w] = s2; }
    __syncthreads();
    if (threadIdx.x == 0) {
        float t1 = 0.f, t2 = 0.f;
        #pragma unroll
        for (int i = 0; i < 8; i++) { t1 += ws1[i]; t2 += ws2[i]; }
        float mean = t1 * (1.0f / DD);
        float var  = t2 * (1.0f / DD) - mean * mean;
        bc[0] = mean;
        bc[1] = rsqrtf(var + 1e-5f);
    }
    __syncthreads();
    out[r * DD + d] = (v - bc[0]) * bc[1] * g[d] + beta[d];
}

// ---------------- SGEMM: C[M,Nc] = A[M,K] @ B[K,Nc] (+bias)(+relu) ----------
template <bool RELU>
__global__ __launch_bounds__(256)
void sgemm_kernel(const float* __restrict__ A, const float* __restrict__ B,
                  const float* __restrict__ bias, float* __restrict__ C,
                  int M, int Nc, int K) {
    __shared__ __align__(16) float As[16][68];
    __shared__ __align__(16) float Bs[16][64];
    int tid = threadIdx.x;
    int tx = tid & 15, ty = tid >> 4;
    int bm = blockIdx.y * 64, bn = blockIdx.x * 64;
    float acc[4][4] = {};
    int arow = tid >> 2, acol4 = (tid & 3) << 2;
    int brow = tid >> 4, bcol4 = (tid & 15) << 2;
    for (int k0 = 0; k0 < K; k0 += 16) {
        float4 a4 = *(const float4*)&A[(size_t)(bm + arow) * K + k0 + acol4];
        As[acol4 + 0][arow] = a4.x; As[acol4 + 1][arow] = a4.y;
        As[acol4 + 2][arow] = a4.z; As[acol4 + 3][arow] = a4.w;
        *(float4*)&Bs[brow][bcol4] =
            *(const float4*)&B[(size_t)(k0 + brow) * Nc + bn + bcol4];
        __syncthreads();
        #pragma unroll
        for (int kk = 0; kk < 16; kk++) {
            float4 ar = *(const float4*)&As[kk][ty * 4];
            float4 br = *(const float4*)&Bs[kk][tx * 4];
            float a_[4] = {ar.x, ar.y, ar.z, ar.w};
            float b_[4] = {br.x, br.y, br.z, br.w};
            #pragma unroll
            for (int i = 0; i < 4; i++)
                #pragma unroll
                for (int j = 0; j < 4; j++)
                    acc[i][j] += a_[i] * b_[j];
        }
        __syncthreads();
    }
    float4 bb = make_float4(0.f, 0.f, 0.f, 0.f);
    if (bias) bb = *(const float4*)&bias[bn + tx * 4];
    #pragma unroll
    for (int i = 0; i < 4; i++) {
        float4 c;
        c.x = acc[i][0] + bb.x; c.y = acc[i][1] + bb.y;
        c.z = acc[i][2] + bb.z; c.w = acc[i][3] + bb.w;
        if (RELU) {
            c.x = fmaxf(c.x, 0.f); c.y = fmaxf(c.y, 0.f);
            c.z = fmaxf(c.z, 0.f); c.w = fmaxf(c.w, 0.f);
        }
        *(float4*)&C[(size_t)(bm + ty * 4 + i) * Nc + bn + tx * 4] = c;
    }
}

// ---------------- flash attention ----------------
// grid (N/128, H), 128 threads. 1 thread = 1 query row. 32-key tiles.
__global__ __launch_bounds__(128)
void attn_kernel(const float* __restrict__ qkv, float* __restrict__ attn_out) {
    const int hh = blockIdx.y;
    const int tid = threadIdx.x;
    const int r = blockIdx.x * 128 + tid;

    __shared__ __align__(16) float Ks[32 * 64];
    __shared__ __align__(16) float Vs[32 * 64];
    __shared__ float Pp[32 * 128];

    float q[64], o[64];
    const float* qrow = qkv + (size_t)r * D3 + hh * HD;
    #pragma unroll
    for (int d4 = 0; d4 < 16; d4++) {
        float4 t = *(const float4*)&qrow[d4 * 4];
        q[d4 * 4 + 0] = t.x * 0.125f;   // fold 1/sqrt(64)
        q[d4 * 4 + 1] = t.y * 0.125f;
        q[d4 * 4 + 2] = t.z * 0.125f;
        q[d4 * 4 + 3] = t.w * 0.125f;
    }
    #pragma unroll
    for (int d = 0; d < 64; d++) o[d] = 0.f;
    float m = -INFINITY, l = 0.f;

    for (int kt = 0; kt < NN / 32; kt++) {
        #pragma unroll
        for (int i = tid; i < 512; i += 128) {
            int j = i >> 4, c = i & 15;
            const float* base = qkv + (size_t)(kt * 32 + j) * D3 + hh * HD + c * 4;
            *(float4*)&Ks[j * 64 + c * 4] = *(const float4*)(base + 256);
            *(float4*)&Vs[j * 64 + c * 4] = *(const float4*)(base + 512);
        }
        __syncthreads();

        float mt = -INFINITY;
        #pragma unroll 4
        for (int j = 0; j < 32; j++) {
            float s = 0.f;
            #pragma unroll
            for (int d4 = 0; d4 < 16; d4++) {
                float4 k4 = *(const float4*)&Ks[j * 64 + d4 * 4];
                s += q[d4 * 4 + 0] * k4.x + q[d4 * 4 + 1] * k4.y
                   + q[d4 * 4 + 2] * k4.z + q[d4 * 4 + 3] * k4.w;
            }
            Pp[j * 128 + tid] = s;
            mt = fmaxf(mt, s);
        }
        float mnew = fmaxf(m, mt);
        float corr = __expf(m - mnew);
        l *= corr;
        #pragma unroll
        for (int d = 0; d < 64; d++) o[d] *= corr;
        m = mnew;

        #pragma unroll 2
        for (int j = 0; j < 32; j++) {
            float p = __expf(Pp[j * 128 + tid] - mnew);
            l += p;
            #pragma unroll
            for (int d4 = 0; d4 < 16; d4++) {
                float4 v4 = *(const float4*)&Vs[j * 64 + d4 * 4];
                o[d4 * 4 + 0] += p * v4.x;
                o[d4 * 4 + 1] += p * v4.y;
                o[d4 * 4 + 2] += p * v4.z;
                o[d4 * 4 + 3] += p * v4.w;
            }
        }
        __syncthreads();
    }
    float inv = 1.0f / l;
    float* orow = attn_out + (size_t)r * DD + hh * HD;
    #pragma unroll
    for (int d4 = 0; d4 < 16; d4++) {
        float4 t;
        t.x = o[d4 * 4 + 0] * inv; t.y = o[d4 * 4 + 1] * inv;
        t.z = o[d4 * 4 + 2] * inv; t.w = o[d4 * 4 + 3] * inv;
        *(float4*)&orow[d4 * 4] = t;
    }
}

// ---------------- launch ----------------
static float* sym_f(const void* sym) {
    void* p = nullptr;
    cudaGetSymbolAddress(&p, sym);
    return (float*)p;
}

extern "C" void kernel_launch(void* const* d_in, const int* in_sizes, int n_in,
                              void* d_out, int out_size) {
    const float* x      = (const float*)d_in[0];
    const int*   edges  = (const int*)  d_in[1];
    const float* W_gcn  = (const float*)d_in[2];
    const float* b_gcn  = (const float*)d_in[3];
    const float* w_qkv  = (const float*)d_in[4];
    const float* b_qkv  = (const float*)d_in[5];
    const float* w_out  = (const float*)d_in[6];
    const float* b_out  = (const float*)d_in[7];
    const float* g1l    = (const float*)d_in[8];
    const float* beta1l = (const float*)d_in[9];
    const float* g1a    = (const float*)d_in[10];
    const float* beta1a = (const float*)d_in[11];
    const float* W1     = (const float*)d_in[12];
    const float* bf1    = (const float*)d_in[13];
    const float* W2     = (const float*)d_in[14];
    const float* bf2    = (const float*)d_in[15];
    const float* g2     = (const float*)d_in[16];
    const float* beta2  = (const float*)d_in[17];
    float* out = (float*)d_out;

    // resolve true device addresses of scratch (host shadow != device symbol!)
    float* p_h    = sym_f(g_h);
    float* p_xl   = sym_f(g_xl);
    float* p_x1   = sym_f(g_x1);
    float* p_qkv  = sym_f(g_qkv);
    float* p_attn = sym_f(g_attn);
    float* p_ao   = sym_f(g_ao);
    float* p_x2   = sym_f(g_x2);
    float* p_h1   = sym_f(g_h1);
    float* p_f2   = sym_f(g_f2);
    float* p_dinv = sym_f(g_dinv);
    int*   p_deg  = (int*)sym_f(g_deg);

    const int E = in_sizes[1] / 2;
    const int* e_src = edges;
    const int* e_dst = edges + E;

    zero_deg_kernel<<<NN / 256, 256>>>(p_deg);
    count_deg_kernel<<<(E + 255) / 256, 256>>>(e_dst, p_deg, E);
    dinv_kernel<<<NN / 256, 256>>>(p_deg, p_dinv);

    sgemm_kernel<false><<<dim3(DD / 64, NN / 64), 256>>>(x, W_gcn, nullptr, p_h, NN, DD, DD);

    selfloop_kernel<<<(NN * DD / 4 + 255) / 256, 256>>>(p_h, p_dinv, b_gcn, p_xl);
    edge_scatter_kernel<<<(E + 3) / 4, 256>>>(e_src, e_dst, p_h, p_dinv, p_xl, E);

    ln_kernel<<<NN, 256>>>(x, p_xl, g1l, beta1l, p_x1);

    sgemm_kernel<false><<<dim3(D3 / 64, NN / 64), 256>>>(p_x1, w_qkv, b_qkv, p_qkv, NN, D3, DD);

    attn_kernel<<<dim3(NN / 128, HH), 128>>>(p_qkv, p_attn);

    sgemm_kernel<false><<<dim3(DD / 64, NN / 64), 256>>>(p_attn, w_out, b_out, p_ao, NN, DD, DD);

    ln_kernel<<<NN, 256>>>(p_x1, p_ao, g1a, beta1a, p_x2);

    sgemm_kernel<true ><<<dim3(2 * DD / 64, NN / 64), 256>>>(p_x2, W1, bf1, p_h1, NN, 2 * DD, DD);
    sgemm_kernel<false><<<dim3(DD / 64, NN / 64), 256>>>(p_h1, W2, bf2, p_f2, NN, DD, 2 * DD);

    ln_kernel<<<NN, 256>>>(p_x2, p_f2, g2, beta2, out);
}

// round 4
// speedup vs baseline: 3.2379x; 3.2379x over previous
#include <cuda_runtime.h>
#include <cuda_bf16.h>
#include <math.h>
#include <stdint.h>

#define NN 4096
#define DD 256
#define HH 4
#define HD 64
#define D3 768

#define CVT_BF16X2_F32(result, a, b) \
    asm("cvt.rn.satfinite.bf16x2.f32 %0, %1, %2;" : "=r"(result) : "f"(b), "f"(a))

__device__ __forceinline__ float fexp2(float x) {
    float y;
    asm("ex2.approx.ftz.f32 %0, %1;" : "=f"(y) : "f"(x));
    return y;
}

// mma.sync m16n8k16 row.col bf16 -> f32 accumulate (sm_80+ baseline ISA)
__device__ __forceinline__ void mma16816(float c[4],
                                         uint32_t a0, uint32_t a1, uint32_t a2, uint32_t a3,
                                         uint32_t b0, uint32_t b1) {
    asm volatile("mma.sync.aligned.m16n8k16.row.col.f32.bf16.bf16.f32 "
                 "{%0,%1,%2,%3}, {%4,%5,%6,%7}, {%8,%9}, {%0,%1,%2,%3};"
                 : "+f"(c[0]), "+f"(c[1]), "+f"(c[2]), "+f"(c[3])
                 : "r"(a0), "r"(a1), "r"(a2), "r"(a3), "r"(b0), "r"(b1));
}

// ======================= scratch (device globals) ==========================
__device__ float g_h   [NN * DD];
__device__ float g_xl  [NN * DD];
__device__ float g_x1  [NN * DD];
__device__ float g_qkv [NN * D3];
__device__ float g_attn[NN * DD];
__device__ float g_ao  [NN * DD];
__device__ float g_x2  [NN * DD];
__device__ float g_h1  [NN * 2 * DD];
__device__ float g_f2  [NN * DD];
__device__ float g_dinv[NN];
__device__ int   g_deg [NN];
// packed bf16: Q/K: [H][N][64]; V^T: [H][64][N]
__device__ __align__(16) __nv_bfloat16 g_qb [HH * NN * HD];
__device__ __align__(16) __nv_bfloat16 g_kb [HH * NN * HD];
__device__ __align__(16) __nv_bfloat16 g_vtb[HH * HD * NN];

// ======================= small kernels ======================================
__global__ void zero_deg_kernel(int* deg) {
    int i = blockIdx.x * blockDim.x + threadIdx.x;
    if (i < NN) deg[i] = 0;
}
__global__ void count_deg_kernel(const int* __restrict__ dst, int* deg, int E) {
    int e = blockIdx.x * blockDim.x + threadIdx.x;
    if (e < E) atomicAdd(&deg[dst[e]], 1);
}
__global__ void dinv_kernel(const int* __restrict__ deg, float* __restrict__ dinv) {
    int i = blockIdx.x * blockDim.x + threadIdx.x;
    if (i < NN) dinv[i] = rsqrtf((float)deg[i] + 1.0f);
}
__global__ void selfloop_kernel(const float* __restrict__ h, const float* __restrict__ dinv,
                                const float* __restrict__ b_gcn, float* __restrict__ xl) {
    int idx = blockIdx.x * blockDim.x + threadIdx.x;
    if (idx >= NN * DD / 4) return;
    int i = idx / (DD / 4), d4 = idx % (DD / 4);
    float c = dinv[i]; c = c * c;
    float4 h4 = *(const float4*)&h[i * DD + d4 * 4];
    float4 b4 = *(const float4*)&b_gcn[d4 * 4];
    float4 o;
    o.x = h4.x * c + b4.x; o.y = h4.y * c + b4.y;
    o.z = h4.z * c + b4.z; o.w = h4.w * c + b4.w;
    *(float4*)&xl[i * DD + d4 * 4] = o;
}
__global__ void edge_scatter_kernel(const int* __restrict__ src, const int* __restrict__ dst,
                                    const float* __restrict__ h, const float* __restrict__ dinv,
                                    float* __restrict__ xl, int E) {
    int e = blockIdx.x * 4 + (threadIdx.x >> 6);
    int lane = threadIdx.x & 63;
    if (e >= E) return;
    int s = src[e], t = dst[e];
    float c = dinv[s] * dinv[t];
    float4 h4 = *(const float4*)&h[s * DD + lane * 4];
    float* o = &xl[t * DD + lane * 4];
    atomicAdd(o + 0, h4.x * c);
    atomicAdd(o + 1, h4.y * c);
    atomicAdd(o + 2, h4.z * c);
    atomicAdd(o + 3, h4.w * c);
}
__global__ void ln_kernel(const float* __restrict__ a, const float* __restrict__ b,
                          const float* __restrict__ g, const float* __restrict__ beta,
                          float* __restrict__ out) {
    int r = blockIdx.x, d = threadIdx.x;
    float v = a[r * DD + d] + b[r * DD + d];
    float s1 = v, s2 = v * v;
    #pragma unroll
    for (int off = 16; off > 0; off >>= 1) {
        s1 += __shfl_xor_sync(0xffffffffu, s1, off);
        s2 += __shfl_xor_sync(0xffffffffu, s2, off);
    }
    __shared__ float ws1[8], ws2[8], bc[2];
    int w = threadIdx.x >> 5;
    if ((threadIdx.x & 31) == 0) { ws1[w] = s1; ws2[w] = s2; }
    __syncthreads();
    if (threadIdx.x == 0) {
        float t1 = 0.f, t2 = 0.f;
        #pragma unroll
        for (int i = 0; i < 8; i++) { t1 += ws1[i]; t2 += ws2[i]; }
        float mean = t1 * (1.0f / DD);
        float var  = t2 * (1.0f / DD) - mean * mean;
        bc[0] = mean; bc[1] = rsqrtf(var + 1e-5f);
    }
    __syncthreads();
    out[r * DD + d] = (v - bc[0]) * bc[1] * g[d] + beta[d];
}

// ======================= SGEMM (fp32) =======================================
template <bool RELU>
__global__ __launch_bounds__(256)
void sgemm_kernel(const float* __restrict__ A, const float* __restrict__ B,
                  const float* __restrict__ bias, float* __restrict__ C,
                  int M, int Nc, int K) {
    __shared__ __align__(16) float As[16][68];
    __shared__ __align__(16) float Bs[16][64];
    int tid = threadIdx.x;
    int tx = tid & 15, ty = tid >> 4;
    int bm = blockIdx.y * 64, bn = blockIdx.x * 64;
    float acc[4][4] = {};
    int arow = tid >> 2, acol4 = (tid & 3) << 2;
    int brow = tid >> 4, bcol4 = (tid & 15) << 2;
    for (int k0 = 0; k0 < K; k0 += 16) {
        float4 a4 = *(const float4*)&A[(size_t)(bm + arow) * K + k0 + acol4];
        As[acol4 + 0][arow] = a4.x; As[acol4 + 1][arow] = a4.y;
        As[acol4 + 2][arow] = a4.z; As[acol4 + 3][arow] = a4.w;
        *(float4*)&Bs[brow][bcol4] = *(const float4*)&B[(size_t)(k0 + brow) * Nc + bn + bcol4];
        __syncthreads();
        #pragma unroll
        for (int kk = 0; kk < 16; kk++) {
            float4 ar = *(const float4*)&As[kk][ty * 4];
            float4 br = *(const float4*)&Bs[kk][tx * 4];
            float a_[4] = {ar.x, ar.y, ar.z, ar.w};
            float b_[4] = {br.x, br.y, br.z, br.w};
            #pragma unroll
            for (int i = 0; i < 4; i++)
                #pragma unroll
                for (int j = 0; j < 4; j++)
                    acc[i][j] += a_[i] * b_[j];
        }
        __syncthreads();
    }
    float4 bb = make_float4(0.f, 0.f, 0.f, 0.f);
    if (bias) bb = *(const float4*)&bias[bn + tx * 4];
    #pragma unroll
    for (int i = 0; i < 4; i++) {
        float4 c;
        c.x = acc[i][0] + bb.x; c.y = acc[i][1] + bb.y;
        c.z = acc[i][2] + bb.z; c.w = acc[i][3] + bb.w;
        if (RELU) {
            c.x = fmaxf(c.x, 0.f); c.y = fmaxf(c.y, 0.f);
            c.z = fmaxf(c.z, 0.f); c.w = fmaxf(c.w, 0.f);
        }
        *(float4*)&C[(size_t)(bm + ty * 4 + i) * Nc + bn + tx * 4] = c;
    }
}

// ======================= bf16 prep =====================================
// Q: scale 0.125 * log2(e) folded (softmax computed base-2).
#define QSCALE (0.125f * 1.4426950408889634f)
__global__ void qk_prep_kernel(const float* __restrict__ qkv) {
    int idx = blockIdx.x * blockDim.x + threadIdx.x;   // [0, 4096*128)
    int dpair = idx & 127;
    int token = idx >> 7;
    int dg = dpair * 2;               // 0..254
    int h  = dg >> 6;
    int d  = dg & 63;
    size_t off = ((size_t)(h * NN + token) * HD + d);
    float2 q2 = *(const float2*)&qkv[(size_t)token * D3 + dg];
    uint32_t qp; CVT_BF16X2_F32(qp, q2.x * QSCALE, q2.y * QSCALE);
    *(uint32_t*)&g_qb[off] = qp;
    float2 k2 = *(const float2*)&qkv[(size_t)token * D3 + 256 + dg];
    uint32_t kp; CVT_BF16X2_F32(kp, k2.x, k2.y);
    *(uint32_t*)&g_kb[off] = kp;
}
__global__ void vt_prep_kernel(const float* __restrict__ qkv) {
    int idx = blockIdx.x * blockDim.x + threadIdx.x;   // [0, 256*2048)
    int dg = idx & 255;
    int tp = idx >> 8;
    int h = dg >> 6, d = dg & 63;
    int t0 = tp * 2;
    float v0 = qkv[(size_t)t0 * D3 + 512 + dg];
    float v1 = qkv[(size_t)(t0 + 1) * D3 + 512 + dg];
    uint32_t vp; CVT_BF16X2_F32(vp, v0, v1);
    *(uint32_t*)&g_vtb[((size_t)(h * HD + d) * NN + t0)] = vp;
}

// ======================= HMMA flash attention ================================
// grid (32, 4): x = q tile (128 rows), y = head. 256 threads = 8 warps.
// warp w owns q rows [w*16, w*16+16). KV tile = 64 keys.
// smem rows padded to 144B (conflict-free fragment loads + 16B-aligned copies).
#define QROWB 144
__global__ __launch_bounds__(256)
void attn_mma_kernel(float* __restrict__ attn_out) {
    __shared__ __align__(16) uint8_t Qs[128 * QROWB];
    __shared__ __align__(16) uint8_t Ks[64 * QROWB];
    __shared__ __align__(16) uint8_t Vs[64 * QROWB];

    const int tid = threadIdx.x;
    const int wid = tid >> 5;
    const int lane = tid & 31;
    const int g = lane >> 2;        // group id (row within m16 / col within n8)
    const int t = lane & 3;         // thread-in-group
    const int hh = blockIdx.y;
    const int qt = blockIdx.x;

    // ---- copy Q tile (128 rows x 128B) ----
    {
        const uint4* src = (const uint4*)(g_qb + (size_t)(hh * NN + qt * 128) * HD);
        #pragma unroll
        for (int i = 0; i < 4; i++) {
            int p = tid + 256 * i;          // 0..1023
            int row = p >> 3, c = p & 7;
            *(uint4*)&Qs[row * QROWB + c * 16] = src[p];
        }
    }
    __syncthreads();

    // ---- Q fragments (loop-invariant) ----
    uint32_t qf[4][4];
    {
        int r0 = wid * 16 + g;
        #pragma unroll
        for (int kc = 0; kc < 4; kc++) {
            int cb = (kc * 16 + 2 * t) * 2;
            qf[kc][0] = *(const uint32_t*)&Qs[r0 * QROWB + cb];
            qf[kc][1] = *(const uint32_t*)&Qs[(r0 + 8) * QROWB + cb];
            qf[kc][2] = *(const uint32_t*)&Qs[r0 * QROWB + cb + 16];
            qf[kc][3] = *(const uint32_t*)&Qs[(r0 + 8) * QROWB + cb + 16];
        }
    }

    float O[8][4];
    #pragma unroll
    for (int n = 0; n < 8; n++)
        #pragma unroll
        for (int i = 0; i < 4; i++) O[n][i] = 0.f;
    float m0 = -INFINITY, m1 = -INFINITY, l0 = 0.f, l1 = 0.f;

    for (int kt = 0; kt < NN / 64; kt++) {
        __syncthreads();
        // ---- copy K tile [64 keys x 64 d] and V^T tile [64 d x 64 keys] ----
        {
            const uint4* ksrc = (const uint4*)(g_kb + (size_t)(hh * NN + kt * 64) * HD);
            #pragma unroll
            for (int i = 0; i < 2; i++) {
                int p = tid + 256 * i;      // 0..511
                int row = p >> 3, c = p & 7;
                *(uint4*)&Ks[row * QROWB + c * 16] = ksrc[p];
                const uint4* vsrc = (const uint4*)(g_vtb + (size_t)(hh * HD + row) * NN + kt * 64);
                *(uint4*)&Vs[row * QROWB + c * 16] = vsrc[c];
            }
        }
        __syncthreads();

        // ---- S = Q K^T : 8 n-tiles (keys), 4 k-steps (dims) ----
        float S[8][4];
        #pragma unroll
        for (int n = 0; n < 8; n++)
            #pragma unroll
            for (int i = 0; i < 4; i++) S[n][i] = 0.f;
        #pragma unroll
        for (int kc = 0; kc < 4; kc++) {
            int cb = (kc * 16 + 2 * t) * 2;
            #pragma unroll
            for (int n = 0; n < 8; n++) {
                uint32_t b0 = *(const uint32_t*)&Ks[(n * 8 + g) * QROWB + cb];
                uint32_t b1 = *(const uint32_t*)&Ks[(n * 8 + g) * QROWB + cb + 16];
                mma16816(S[n], qf[kc][0], qf[kc][1], qf[kc][2], qf[kc][3], b0, b1);
            }
        }

        // ---- online softmax (base 2; scale folded into Q) ----
        float mt0 = -INFINITY, mt1 = -INFINITY;
        #pragma unroll
        for (int n = 0; n < 8; n++) {
            mt0 = fmaxf(mt0, fmaxf(S[n][0], S[n][1]));
            mt1 = fmaxf(mt1, fmaxf(S[n][2], S[n][3]));
        }
        mt0 = fmaxf(mt0, __shfl_xor_sync(0xffffffffu, mt0, 1));
        mt0 = fmaxf(mt0, __shfl_xor_sync(0xffffffffu, mt0, 2));
        mt1 = fmaxf(mt1, __shfl_xor_sync(0xffffffffu, mt1, 1));
        mt1 = fmaxf(mt1, __shfl_xor_sync(0xffffffffu, mt1, 2));
        float mn0 = fmaxf(m0, mt0), mn1 = fmaxf(m1, mt1);
        float corr0 = fexp2(m0 - mn0), corr1 = fexp2(m1 - mn1);
        m0 = mn0; m1 = mn1;

        uint32_t pb[8][2];
        float s0 = 0.f, s1 = 0.f;
        #pragma unroll
        for (int n = 0; n < 8; n++) {
            float p0 = fexp2(S[n][0] - mn0);
            float p1 = fexp2(S[n][1] - mn0);
            float p2 = fexp2(S[n][2] - mn1);
            float p3 = fexp2(S[n][3] - mn1);
            s0 += p0 + p1; s1 += p2 + p3;
            CVT_BF16X2_F32(pb[n][0], p0, p1);
            CVT_BF16X2_F32(pb[n][1], p2, p3);
        }
        s0 += __shfl_xor_sync(0xffffffffu, s0, 1);
        s0 += __shfl_xor_sync(0xffffffffu, s0, 2);
        s1 += __shfl_xor_sync(0xffffffffu, s1, 1);
        s1 += __shfl_xor_sync(0xffffffffu, s1, 2);
        l0 = l0 * corr0 + s0;
        l1 = l1 * corr1 + s1;
        #pragma unroll
        for (int n = 0; n < 8; n++) {
            O[n][0] *= corr0; O[n][1] *= corr0;
            O[n][2] *= corr1; O[n][3] *= corr1;
        }

        // ---- O += P V^T : P fragments = packed S C-fragments ----
        #pragma unroll
        for (int kc = 0; kc < 4; kc++) {
            uint32_t a0 = pb[2 * kc][0], a1 = pb[2 * kc][1];
            uint32_t a2 = pb[2 * kc + 1][0], a3 = pb[2 * kc + 1][1];
            int cb = (kc * 16 + 2 * t) * 2;
            #pragma unroll
            for (int n = 0; n < 8; n++) {
                uint32_t b0 = *(const uint32_t*)&Vs[(n * 8 + g) * QROWB + cb];
                uint32_t b1 = *(const uint32_t*)&Vs[(n * 8 + g) * QROWB + cb + 16];
                mma16816(O[n], a0, a1, a2, a3, b0, b1);
            }
        }
    }

    // ---- write out ----
    float inv0 = 1.0f / l0, inv1 = 1.0f / l1;
    int r0 = qt * 128 + wid * 16 + g;
    #pragma unroll
    for (int n = 0; n < 8; n++) {
        int dcol = hh * HD + n * 8 + 2 * t;
        float2 v0 = make_float2(O[n][0] * inv0, O[n][1] * inv0);
        float2 v1 = make_float2(O[n][2] * inv1, O[n][3] * inv1);
        *(float2*)&attn_out[(size_t)r0 * DD + dcol] = v0;
        *(float2*)&attn_out[(size_t)(r0 + 8) * DD + dcol] = v1;
    }
}

// ======================= launch =============================================
static float* sym_f(const void* sym) {
    void* p = nullptr;
    cudaGetSymbolAddress(&p, sym);
    return (float*)p;
}

extern "C" void kernel_launch(void* const* d_in, const int* in_sizes, int n_in,
                              void* d_out, int out_size) {
    const float* x      = (const float*)d_in[0];
    const int*   edges  = (const int*)  d_in[1];
    const float* W_gcn  = (const float*)d_in[2];
    const float* b_gcn  = (const float*)d_in[3];
    const float* w_qkv  = (const float*)d_in[4];
    const float* b_qkv  = (const float*)d_in[5];
    const float* w_out  = (const float*)d_in[6];
    const float* b_out  = (const float*)d_in[7];
    const float* g1l    = (const float*)d_in[8];
    const float* beta1l = (const float*)d_in[9];
    const float* g1a    = (const float*)d_in[10];
    const float* beta1a = (const float*)d_in[11];
    const float* W1     = (const float*)d_in[12];
    const float* bf1    = (const float*)d_in[13];
    const float* W2     = (const float*)d_in[14];
    const float* bf2    = (const float*)d_in[15];
    const float* g2     = (const float*)d_in[16];
    const float* beta2  = (const float*)d_in[17];
    float* out = (float*)d_out;

    float* p_h    = sym_f(g_h);
    float* p_xl   = sym_f(g_xl);
    float* p_x1   = sym_f(g_x1);
    float* p_qkv  = sym_f(g_qkv);
    float* p_attn = sym_f(g_attn);
    float* p_ao   = sym_f(g_ao);
    float* p_x2   = sym_f(g_x2);
    float* p_h1   = sym_f(g_h1);
    float* p_f2   = sym_f(g_f2);
    float* p_dinv = sym_f(g_dinv);
    int*   p_deg  = (int*)sym_f(g_deg);

    const int E = in_sizes[1] / 2;
    const int* e_src = edges;
    const int* e_dst = edges + E;

    zero_deg_kernel<<<NN / 256, 256>>>(p_deg);
    count_deg_kernel<<<(E + 255) / 256, 256>>>(e_dst, p_deg, E);
    dinv_kernel<<<NN / 256, 256>>>(p_deg, p_dinv);

    sgemm_kernel<false><<<dim3(DD / 64, NN / 64), 256>>>(x, W_gcn, nullptr, p_h, NN, DD, DD);

    selfloop_kernel<<<(NN * DD / 4 + 255) / 256, 256>>>(p_h, p_dinv, b_gcn, p_xl);
    edge_scatter_kernel<<<(E + 3) / 4, 256>>>(e_src, e_dst, p_h, p_dinv, p_xl, E);

    ln_kernel<<<NN, 256>>>(x, p_xl, g1l, beta1l, p_x1);

    sgemm_kernel<false><<<dim3(D3 / 64, NN / 64), 256>>>(p_x1, w_qkv, b_qkv, p_qkv, NN, D3, DD);

    qk_prep_kernel<<<2048, 256>>>(p_qkv);
    vt_prep_kernel<<<2048, 256>>>(p_qkv);

    attn_mma_kernel<<<dim3(NN / 128, HH), 256>>>(p_attn);

    sgemm_kernel<false><<<dim3(DD / 64, NN / 64), 256>>>(p_attn, w_out, b_out, p_ao, NN, DD, DD);

    ln_kernel<<<NN, 256>>>(p_x1, p_ao, g1a, beta1a, p_x2);

    sgemm_kernel<true ><<<dim3(2 * DD / 64, NN / 64), 256>>>(p_x2, W1, bf1, p_h1, NN, 2 * DD, DD);
    sgemm_kernel<false><<<dim3(DD / 64, NN / 64), 256>>>(p_h1, W2, bf2, p_f2, NN, DD, 2 * DD);

    ln_kernel<<<NN, 256>>>(p_x2, p_f2, g2, beta2, out);
}